// round 17
// baseline (speedup 1.0000x reference)
#include <cuda_runtime.h>
#include <cuda_fp16.h>
#include <cstdint>

// ---------------------------------------------------------------------------
// Problem constants
// ---------------------------------------------------------------------------
static constexpr int BATCH = 4;
static constexpr int TQ    = 2048;
static constexpr int TC    = 2048;
static constexpr int HDIM  = 1024;
static constexpr int NH    = 16;
static constexpr int DH    = 64;
static constexpr int MROWS = BATCH * TQ;   // 8192

// ---------------------------------------------------------------------------
// Scratch (no allocations allowed -> __device__ globals).  All fp16.
// ---------------------------------------------------------------------------
__device__ alignas(256) __half s_q16[(size_t)MROWS * HDIM];    // query fp16
__device__ alignas(256) __half s_c16[(size_t)MROWS * HDIM];    // context fp16
__device__ alignas(256) __half s_w16[4 * (size_t)HDIM * HDIM]; // Wq,Wk,Wv,Wo fp16
__device__ alignas(256) __half s_qph[(size_t)MROWS * HDIM];    // Q proj (pre /8)
__device__ alignas(256) __half s_kph[(size_t)MROWS * HDIM];    // K proj
__device__ alignas(256) __half s_vph[(size_t)MROWS * HDIM];    // V proj
__device__ alignas(256) __half s_ap16[(size_t)MROWS * HDIM];   // attn out

// ---------------------------------------------------------------------------
// Helpers
// ---------------------------------------------------------------------------
__device__ __forceinline__ uint32_t smem_u32(const void* p) {
    uint32_t a;
    asm("{ .reg .u64 t; cvta.to.shared.u64 t, %1; cvt.u32.u64 %0, t; }" : "=r"(a) : "l"(p));
    return a;
}
#define CPA16(dst, src) \
    asm volatile("cp.async.cg.shared.global [%0], [%1], 16;" :: "r"(dst), "l"(src))
#define CPA_COMMIT() asm volatile("cp.async.commit_group;" ::: "memory")
#define CPA_WAIT0()  asm volatile("cp.async.wait_group 0;" ::: "memory")
#define CPA_WAIT1()  asm volatile("cp.async.wait_group 1;" ::: "memory")

// ldmatrix wrappers (m8n8 b16 tiles).  X4 variants fetch TWO mma fragments.
#define LDSM_X4(r, a) \
    asm volatile("ldmatrix.sync.aligned.m8n8.x4.shared.b16 {%0,%1,%2,%3}, [%4];" \
                 : "=r"((r)[0]), "=r"((r)[1]), "=r"((r)[2]), "=r"((r)[3]) : "r"(a))
#define LDSM_X4T(r, a) \
    asm volatile("ldmatrix.sync.aligned.m8n8.x4.trans.shared.b16 {%0,%1,%2,%3}, [%4];" \
                 : "=r"((r)[0]), "=r"((r)[1]), "=r"((r)[2]), "=r"((r)[3]) : "r"(a))

// mma.m16n8k16 row.col f32 += f16 * f16
#define MMAF16(c, a, b0_, b1_) \
    asm volatile("mma.sync.aligned.m16n8k16.row.col.f32.f16.f16.f32 " \
        "{%0,%1,%2,%3}, {%4,%5,%6,%7}, {%8,%9}, {%0,%1,%2,%3};" \
        : "+f"((c)[0]), "+f"((c)[1]), "+f"((c)[2]), "+f"((c)[3]) \
        : "r"((a)[0]), "r"((a)[1]), "r"((a)[2]), "r"((a)[3]), "r"(b0_), "r"(b1_))

__device__ __forceinline__ uint32_t pack_f16(float lo, float hi) {
    __half2 v = __halves2half2(__float2half_rn(lo), __float2half_rn(hi));
    return *reinterpret_cast<uint32_t*>(&v);
}

// ---------------------------------------------------------------------------
// Split kernels: fp32 -> fp16.  Merged launches (weights x4, activations x2).
// ---------------------------------------------------------------------------
__device__ __forceinline__ void cvt_store4(__half* p, float4 v) {
    *(__half2*)(p + 0) = __halves2half2(__float2half_rn(v.x), __float2half_rn(v.y));
    *(__half2*)(p + 2) = __halves2half2(__float2half_rn(v.z), __float2half_rn(v.w));
}

__global__ __launch_bounds__(256) void split_w4(
    const float4* __restrict__ s0, const float4* __restrict__ s1,
    const float4* __restrict__ s2, const float4* __restrict__ s3,
    __half* __restrict__ d)
{
    int r = blockIdx.x >> 8;                    // 0..3
    const float4* src = (r == 0) ? s0 : (r == 1) ? s1 : (r == 2) ? s2 : s3;
    __half* dst = d + (size_t)r * HDIM * HDIM;
    int base = (blockIdx.x & 255) * 1024 + threadIdx.x;
    float4 v[4];
#pragma unroll
    for (int u = 0; u < 4; u++) v[u] = src[base + u * 256];
#pragma unroll
    for (int u = 0; u < 4; u++) cvt_store4(dst + 4 * (size_t)(base + u * 256), v[u]);
}

__global__ __launch_bounds__(256) void split_a2(
    const float4* __restrict__ s0, const float4* __restrict__ s1,
    __half* __restrict__ d0, __half* __restrict__ d1)
{
    int r = blockIdx.x >> 11;                   // 0..1
    const float4* src = r ? s1 : s0;
    __half* dst = r ? d1 : d0;
    int base = (blockIdx.x & 2047) * 1024 + threadIdx.x;
    float4 v[4];
#pragma unroll
    for (int u = 0; u < 4; u++) v[u] = src[base + u * 256];
#pragma unroll
    for (int u = 0; u < 4; u++) cvt_store4(dst + 4 * (size_t)(base + u * 256), v[u]);
}

// ---------------------------------------------------------------------------
// F16 GEMM:  C[M,1024] = A @ W + bias   (single fp16 operands, fp32 accum)
// Block tile 128x256x64, 8 warps (2x4), warp tile 64x64, occ 1.
// smem per buffer: A 128x144B = 18432 | B 64x528B = 33792 -> 52224 B.
// Per k-tile per warp: 32 LDSM : 128 MMA.
// ---------------------------------------------------------------------------
static constexpr int GBM = 128, GBN = 256, GBK = 64;
static constexpr int G_LDA  = 144;             // bytes per A row (64 h + 8 pad)
static constexpr int G_LDB  = 528;             // bytes per B row (256 h + 8 pad)
static constexpr int G_OFF_B = GBM * G_LDA;    // 18432
static constexpr int G_BUF   = G_OFF_B + GBK * G_LDB;   // 52224
static constexpr int GEMM_SMEM = 2 * G_BUF;    // 104448

__device__ __forceinline__ void gemm_issue_tile(
    uint32_t bb,
    const __half* __restrict__ A, const __half* __restrict__ B,
    int m0, int n0, int k0, int t)
{
    // A: 128 rows x 8 chunks (16 B) = 1024 chunks, 4 per thread
#pragma unroll
    for (int i = 0; i < 4; i++) {
        int idx = t + i * 256;          // 0..1023
        int r = idx >> 3, c = idx & 7;
        CPA16(bb + r * G_LDA + c * 16, A + (size_t)(m0 + r) * HDIM + k0 + c * 8);
    }
    // B: 64 rows x 32 chunks = 2048 chunks, 8 per thread
#pragma unroll
    for (int i = 0; i < 8; i++) {
        int idx = t + i * 256;          // 0..2047
        int r = idx >> 5, c = idx & 31;
        CPA16(bb + G_OFF_B + r * G_LDB + c * 16,
              B + (size_t)(k0 + r) * HDIM + n0 + c * 8);
    }
}

__global__ __launch_bounds__(256, 1) void gemm_mma(
    const __half* __restrict__ A, const __half* __restrict__ B,
    const float* __restrict__ bias, float scale,
    float* __restrict__ Cf, __half* __restrict__ Ch)
{
    extern __shared__ char dsm[];
    const uint32_t sbase = smem_u32(dsm);

    const int t    = threadIdx.x;
    const int w    = t >> 5;
    const int lane = t & 31;
    const int wm   = w >> 2;   // 0..1  rows wm*64
    const int wn   = w & 3;    // 0..3  cols wn*64
    const int m0   = blockIdx.y * GBM;
    const int n0   = blockIdx.x * GBN;

    float C[4][8][4];
#pragma unroll
    for (int i = 0; i < 4; i++)
#pragma unroll
        for (int j = 0; j < 8; j++)
#pragma unroll
            for (int e = 0; e < 4; e++) C[i][j][e] = 0.0f;

    const uint32_t a_lane = (uint32_t)((wm * 64 + (lane & 15)) * G_LDA
                                       + (((lane >> 4) & 1) << 4));
    // x4-trans B: lanes 0-15 -> rows, col base; lanes 16-31 -> rows, col+8
    const uint32_t b_lane = (uint32_t)((lane & 15) * G_LDB
                                       + (((lane >> 4) & 1) << 4) + wn * 128);

    gemm_issue_tile(sbase, A, B, m0, n0, 0, t);
    CPA_COMMIT();

    for (int kt = 0; kt < HDIM / GBK; kt++) {
        const int cur = kt & 1;
        if (kt < HDIM / GBK - 1) {
            gemm_issue_tile(sbase + ((kt + 1) & 1) * G_BUF,
                            A, B, m0, n0, (kt + 1) * GBK, t);
            CPA_COMMIT();
            CPA_WAIT1();
        } else {
            CPA_WAIT0();
        }
        __syncthreads();

        const uint32_t bA = sbase + cur * G_BUF;
        const uint32_t bB = bA + G_OFF_B;

#pragma unroll
        for (int ks = 0; ks < 4; ks++) {
            uint32_t af[4][4];
#pragma unroll
            for (int i = 0; i < 4; i++)
                LDSM_X4(af[i], bA + a_lane + (uint32_t)(i * 16 * G_LDA + ks * 32));
#pragma unroll
            for (int jp = 0; jp < 4; jp++) {
                uint32_t bf[4];
                LDSM_X4T(bf, bB + b_lane + (uint32_t)(ks * 16 * G_LDB + jp * 32));
#pragma unroll
                for (int i = 0; i < 4; i++) {
                    MMAF16(C[i][2 * jp + 0], af[i], bf[0], bf[1]);
                    MMAF16(C[i][2 * jp + 1], af[i], bf[2], bf[3]);
                }
            }
        }
        __syncthreads();
    }

    // ---- epilogue: direct global stores, bias from registers ----
    const int erow = m0 + wm * 64 + (lane >> 2);
    const int ecol = n0 + wn * 64 + 2 * (lane & 3);
    float2 bb[8];
#pragma unroll
    for (int j = 0; j < 8; j++)
        bb[j] = *(const float2*)(bias + ecol + j * 8);

#pragma unroll
    for (int i = 0; i < 4; i++) {
        const int gr0 = erow + i * 16;
#pragma unroll
        for (int j = 0; j < 8; j++) {
            const int gc = ecol + j * 8;
            float v0 = C[i][j][0] + bb[j].x;
            float v1 = C[i][j][1] + bb[j].y;
            float v2 = C[i][j][2] + bb[j].x;
            float v3 = C[i][j][3] + bb[j].y;
            if (Cf) {
                *(float2*)(Cf + (size_t)gr0 * HDIM + gc)       = make_float2(v0, v1);
                *(float2*)(Cf + (size_t)(gr0 + 8) * HDIM + gc) = make_float2(v2, v3);
            } else {
                *(__half2*)(Ch + (size_t)gr0 * HDIM + gc) =
                    __halves2half2(__float2half_rn(v0 * scale),
                                   __float2half_rn(v1 * scale));
                *(__half2*)(Ch + (size_t)(gr0 + 8) * HDIM + gc) =
                    __halves2half2(__float2half_rn(v2 * scale),
                                   __float2half_rn(v3 * scale));
            }
        }
    }
}

// ---------------------------------------------------------------------------
// FlashAttention-2-style fused attention, single-fp16 operands.
// Q-tile 256 rows, warp owns 32 q-rows (2 m-tiles) -> K/V fragments feed 2x
// the MMAs per LDSM.  ACH=128 chunks, occ 1.
// smem: Q 256x144B = 36864 | 2 x (K,V 128x144B) = 73728 -> 110592 B
// ---------------------------------------------------------------------------
static constexpr int AQT     = 256;
static constexpr int ACH     = 128;
static constexpr int A_LDB   = 144;
static constexpr int A_QTILE = AQT * A_LDB;     // 36864
static constexpr int A_KVT   = ACH * A_LDB;     // 18432
static constexpr int A_OFFKV = A_QTILE;         // 36864
static constexpr int A_KVBUF = 2 * A_KVT;       // 36864
static constexpr int ATTN_SMEM = A_OFFKV + 2 * A_KVBUF;   // 110592

__device__ __forceinline__ void attn_issue_kv(uint32_t buf, size_t koff,
                                              int ch, int t)
{
    // K,V: 128 rows x 8 chunks each = 1024 chunks -> 4 per thread each
#pragma unroll
    for (int i = 0; i < 4; i++) {
        int idx = t + i * 256;              // 0..1023
        int r = idx >> 3, c = idx & 7;
        uint32_t d = (uint32_t)(r * A_LDB + c * 16);
        size_t so = koff + (size_t)(ch * ACH + r) * HDIM + c * 8;
        CPA16(buf + d,         s_kph + so);
        CPA16(buf + A_KVT + d, s_vph + so);
    }
}

__global__ __launch_bounds__(256, 1) void attn_fa()
{
    extern __shared__ char sm[];
    const uint32_t S  = smem_u32(sm);
    const uint32_t Qh = S;

    const int t    = threadIdx.x;
    const int w    = t >> 5;
    const int lane = t & 31;
    const int qt   = blockIdx.x;
    const int bh   = blockIdx.y;
    const int b    = bh >> 4;
    const int h    = bh & 15;

    const size_t qoff = (size_t)(b * TQ + qt * AQT) * HDIM + h * DH;
    const size_t koff = (size_t)(b * TC) * HDIM + h * DH;

    // ---- issue Q tile: 256 rows x 8 chunks = 2048 chunks, 8 per thread ----
#pragma unroll
    for (int i = 0; i < 8; i++) {
        int idx = t + i * 256;              // 0..2047
        int r = idx >> 3, c = idx & 7;
        uint32_t d = (uint32_t)(r * A_LDB + c * 16);
        CPA16(Qh + d, s_qph + qoff + (size_t)r * HDIM + c * 8);
    }
    attn_issue_kv(S + A_OFFKV, koff, 0, t);
    CPA_COMMIT();

    float O[2][8][4];
#pragma unroll
    for (int m = 0; m < 2; m++)
#pragma unroll
        for (int j = 0; j < 8; j++)
#pragma unroll
            for (int i = 0; i < 4; i++) O[m][j][i] = 0.0f;
    float rs[2][2] = {{0.0f, 0.0f}, {0.0f, 0.0f}};

    uint32_t qf[2][4][4];

    // ldmatrix per-lane address pieces
    const uint32_t q_lane0 = (uint32_t)((w * 32 + (lane & 15)) * A_LDB
                                        + (((lane >> 4) & 1) << 4));
    const uint32_t k_lane = (uint32_t)((lane & 7) * A_LDB
                                       + (((lane >> 3) & 1) << 4)
                                       + (((lane >> 4) & 1) * 8) * A_LDB);
    const uint32_t v_lane = (uint32_t)((lane & 15) * A_LDB
                                       + (((lane >> 4) & 1) << 4));

    for (int ch = 0; ch < TC / ACH; ch++) {
        CPA_WAIT0();
        __syncthreads();

        if (ch + 1 < TC / ACH) {
            attn_issue_kv(S + A_OFFKV + ((ch + 1) & 1) * A_KVBUF, koff, ch + 1, t);
            CPA_COMMIT();
        }
        if (ch == 0) {
#pragma unroll
            for (int m = 0; m < 2; m++)
#pragma unroll
                for (int ks = 0; ks < 4; ks++)
                    LDSM_X4(qf[m][ks],
                            Qh + q_lane0 + (uint32_t)(m * 16 * A_LDB) + ks * 32);
        }

        const uint32_t kb  = S + A_OFFKV + (ch & 1) * A_KVBUF;
        const uint32_t Khb = kb;
        const uint32_t Vhb = kb + A_KVT;

#pragma unroll
        for (int kp = 0; kp < 8; kp++) {
            // ---- S pair (n-tiles 2kp, 2kp+1) for both m tiles ----
            float s[2][2][4];
#pragma unroll
            for (int m = 0; m < 2; m++)
#pragma unroll
                for (int n = 0; n < 2; n++)
#pragma unroll
                    for (int e = 0; e < 4; e++) s[m][n][e] = 0.0f;
            const uint32_t krow = (uint32_t)(16 * kp * A_LDB) + k_lane;
#pragma unroll
            for (int ks = 0; ks < 4; ks++) {
                uint32_t kf[4];
                LDSM_X4(kf, Khb + krow + ks * 32);
#pragma unroll
                for (int m = 0; m < 2; m++) {
                    MMAF16(s[m][0], qf[m][ks], kf[0], kf[1]);
                    MMAF16(s[m][1], qf[m][ks], kf[2], kf[3]);
                }
            }
            uint32_t pH[2][4];
#pragma unroll
            for (int m = 0; m < 2; m++) {
                float p0 = __expf(s[m][0][0]), p1 = __expf(s[m][0][1]);
                float p2 = __expf(s[m][0][2]), p3 = __expf(s[m][0][3]);
                float p4 = __expf(s[m][1][0]), p5 = __expf(s[m][1][1]);
                float p6 = __expf(s[m][1][2]), p7 = __expf(s[m][1][3]);
                rs[m][0] += p0 + p1 + p4 + p5;
                rs[m][1] += p2 + p3 + p6 + p7;
                pH[m][0] = pack_f16(p0, p1);
                pH[m][1] = pack_f16(p2, p3);
                pH[m][2] = pack_f16(p4, p5);
                pH[m][3] = pack_f16(p6, p7);
            }

            // ---- PV via x4-trans V loads (jo pairs), both m tiles ----
            const uint32_t vrow = (uint32_t)(16 * kp * A_LDB) + v_lane;
#pragma unroll
            for (int jp = 0; jp < 4; jp++) {
                uint32_t vf[4];
                LDSM_X4T(vf, Vhb + vrow + jp * 32);
#pragma unroll
                for (int m = 0; m < 2; m++) {
                    MMAF16(O[m][2 * jp + 0], pH[m], vf[0], vf[1]);
                    MMAF16(O[m][2 * jp + 1], pH[m], vf[2], vf[3]);
                }
            }
        }
    }

#pragma unroll
    for (int m = 0; m < 2; m++) {
        rs[m][0] += __shfl_xor_sync(0xffffffffu, rs[m][0], 1);
        rs[m][0] += __shfl_xor_sync(0xffffffffu, rs[m][0], 2);
        rs[m][1] += __shfl_xor_sync(0xffffffffu, rs[m][1], 1);
        rs[m][1] += __shfl_xor_sync(0xffffffffu, rs[m][1], 2);
    }

    // ---- epilogue: normalize, fp16 ----
    const int ocol0 = h * DH + 2 * (lane & 3);
#pragma unroll
    for (int m = 0; m < 2; m++) {
        const int orow = b * TQ + qt * AQT + w * 32 + m * 16 + (lane >> 2);
        const float inv0 = 1.0f / rs[m][0];
        const float inv1 = 1.0f / rs[m][1];
#pragma unroll
        for (int jo = 0; jo < 8; jo++) {
            int col = ocol0 + jo * 8;
            *(__half2*)(s_ap16 + (size_t)orow * HDIM + col) =
                __halves2half2(__float2half_rn(O[m][jo][0] * inv0),
                               __float2half_rn(O[m][jo][1] * inv0));
            *(__half2*)(s_ap16 + (size_t)(orow + 8) * HDIM + col) =
                __halves2half2(__float2half_rn(O[m][jo][2] * inv1),
                               __float2half_rn(O[m][jo][3] * inv1));
        }
    }
}

// ---------------------------------------------------------------------------
// kernel_launch: graph-capturable, allocation-free.
// Input order: query, context, Wq, bq, Wk, bk, Wv, bv, Wo, bo
// ---------------------------------------------------------------------------
extern "C" void kernel_launch(void* const* d_in, const int* in_sizes, int n_in,
                              void* d_out, int out_size)
{
    const float* query   = (const float*)d_in[0];
    const float* context = (const float*)d_in[1];
    const float* Wq = (const float*)d_in[2];
    const float* bq = (const float*)d_in[3];
    const float* Wk = (const float*)d_in[4];
    const float* bk = (const float*)d_in[5];
    const float* Wv = (const float*)d_in[6];
    const float* bv = (const float*)d_in[7];
    const float* Wo = (const float*)d_in[8];
    const float* bo = (const float*)d_in[9];
    float* out = (float*)d_out;

    __half *q16, *c16, *wt, *qph, *kph, *vph, *ap16;
    cudaGetSymbolAddress((void**)&q16,  s_q16);
    cudaGetSymbolAddress((void**)&c16,  s_c16);
    cudaGetSymbolAddress((void**)&wt,   s_w16);
    cudaGetSymbolAddress((void**)&qph,  s_qph);
    cudaGetSymbolAddress((void**)&kph,  s_kph);
    cudaGetSymbolAddress((void**)&vph,  s_vph);
    cudaGetSymbolAddress((void**)&ap16, s_ap16);

    const size_t WSZ = (size_t)HDIM * HDIM;
    __half* wq16 = wt + 0 * WSZ;
    __half* wk16 = wt + 1 * WSZ;
    __half* wv16 = wt + 2 * WSZ;
    __half* wo16 = wt + 3 * WSZ;

    cudaFuncSetAttribute(attn_fa, cudaFuncAttributeMaxDynamicSharedMemorySize,
                         ATTN_SMEM);
    cudaFuncSetAttribute(gemm_mma, cudaFuncAttributeMaxDynamicSharedMemorySize,
                         GEMM_SMEM);

    dim3 ggrid(HDIM / GBN, MROWS / GBM);    // (4, 64)

    split_a2<<<4096, 256>>>((const float4*)query, (const float4*)context,
                            q16, c16);
    split_w4<<<1024, 256>>>((const float4*)Wq, (const float4*)Wk,
                            (const float4*)Wv, (const float4*)Wo, wt);

    gemm_mma<<<ggrid, 256, GEMM_SMEM>>>(q16, wq16, bq, 0.125f, nullptr, qph);
    gemm_mma<<<ggrid, 256, GEMM_SMEM>>>(c16, wk16, bk, 1.0f,   nullptr, kph);
    gemm_mma<<<ggrid, 256, GEMM_SMEM>>>(c16, wv16, bv, 1.0f,   nullptr, vph);

    attn_fa<<<dim3(TQ / AQT, BATCH * NH), 256, ATTN_SMEM>>>();

    gemm_mma<<<ggrid, 256, GEMM_SMEM>>>(ap16, wo16, bo, 1.0f, out, nullptr);
}